// round 16
// baseline (speedup 1.0000x reference)
#include <cuda_runtime.h>
#include <math.h>

#define NN 8
#define C  64
#define HH 64
#define WW 64
#define HWP 4096            // H*W
#define HP 66               // padded
#define CO 128

typedef unsigned long long u64;

// ---- f32x2 helpers (exact fp32, 2 lanes per instruction) ----
__device__ __forceinline__ u64 dup2(float v) {
    u64 r; asm("mov.b64 %0,{%1,%1};" : "=l"(r) : "f"(v)); return r;
}
__device__ __forceinline__ void fma2(u64& d, u64 a, u64 b) {
    asm("fma.rn.f32x2 %0,%1,%2,%0;" : "+l"(d) : "l"(a), "l"(b));
}
__device__ __forceinline__ float2 up2(u64 v) {
    float2 r; asm("mov.b64 {%0,%1},%2;" : "=f"(r.x), "=f"(r.y) : "l"(v)); return r;
}

// ---------------- scratch ----------------
__device__ float g_pooled[NN * C];
__device__ __align__(16) float g_x2[NN * HWP * C];
__device__ __align__(16) float g_xpad[NN * HP * HP * C];   // zero-init; border never written

// ---------------- K1: global average pool (1024 thr, 1 float4/thread) ----------------
__global__ void __launch_bounds__(1024)
k_pool(const float* __restrict__ x) {
    int nc = blockIdx.x;
    int t = threadIdx.x;
    float4 v = reinterpret_cast<const float4*>(x + nc * HWP)[t];
    float a = (v.x + v.y) + (v.z + v.w);
    #pragma unroll
    for (int o = 16; o >= 1; o >>= 1) a += __shfl_xor_sync(0xffffffffu, a, o);
    __shared__ float red[32];
    if ((t & 31) == 0) red[t >> 5] = a;
    __syncthreads();
    if (t < 32) {
        float s = red[t];
        #pragma unroll
        for (int o = 16; o >= 1; o >>= 1) s += __shfl_xor_sync(0xffffffffu, s, o);
        if (t == 0) g_pooled[nc] = s * (1.f / (float)HWP);
    }
}

// ---------------- K2 (fused): gain MLP + gain/refl fuse + input_proj GEMM ----------------
// 64 px/block, 512 blocks. Produces g_x2 AND g_xpad in one pass.
#define FUSE_SMEM ((64 * 65 + 64 * 72 + 64 * 64) * 4)

__global__ void __launch_bounds__(256)
k_fuse2(const float* __restrict__ x, const float* __restrict__ refl,
        const float* __restrict__ tap_w, const float* __restrict__ tap_b,
        const float* __restrict__ w1, const float* __restrict__ b1,
        const float* __restrict__ w2, const float* __restrict__ b2,
        const float* __restrict__ iw, const float* __restrict__ ib) {
    extern __shared__ __align__(16) float dyn[];
    float* s33 = dyn;                  // [c][px] stride 65 (conflict-free transpose reads)
    float* xsT = dyn + 64 * 65;        // [k][px] stride 72 (16B-aligned rows for GEMM)
    float* Ws  = xsT + 64 * 72;        // inp weights [k][c]
    __shared__ float pl[C];
    __shared__ float h[16];
    __shared__ float gn[C];
    __shared__ float rfl[64];
    int t = threadIdx.x;
    int pix0 = blockIdx.x * 64;
    int n = pix0 >> 12;
    int hw0 = pix0 & 4095;

    // weights + pooled + refl
    {
        const float4* wsrc = reinterpret_cast<const float4*>(iw);
        float4* wdst = reinterpret_cast<float4*>(Ws);
        for (int i = t; i < 64 * 64 / 4; i += 256) wdst[i] = wsrc[i];
    }
    if (t < 64) pl[t] = g_pooled[n * C + t];
    if (t >= 64 && t < 128) rfl[t - 64] = refl[n * HWP + hw0 + (t - 64)];
    __syncthreads();
    if (t < 16) {
        float a = b1[t];
        #pragma unroll 16
        for (int c = 0; c < C; c++) a += pl[c] * w1[c * 16 + t];
        h[t] = fmaxf(a, 0.f);
    }
    __syncthreads();
    if (t < 64) {
        float a = b2[t];
        #pragma unroll
        for (int j = 0; j < 16; j++) a += h[j] * w2[j * C + t];
        gn[t] = 1.f + 1.f / (1.f + expf(-a));
    }
    __syncthreads();

    // load x + apply gain + refl; write both smem copies
    {
        int px = t & 63;
        int ch = t >> 6;               // 0..3
        float rv = rfl[px];
        #pragma unroll 4
        for (int i = 0; i < 16; i++) {
            int c = i * 4 + ch;
            float val = x[(n * C + c) * HWP + hw0 + px] * gn[c];
            val += fmaxf(rv * tap_w[c] + tap_b[c], 0.f);
            s33[c * 65 + px] = val;
            xsT[c * 72 + px] = val;
        }
    }
    __syncthreads();

    // write g_x2 coalesced (transpose via s33)
    {
        int cq = t & 15;
        int pxb = t >> 4;              // 0..15
        #pragma unroll
        for (int pass = 0; pass < 4; pass++) {
            int px = pass * 16 + pxb;
            float4 v;
            v.x = s33[(4 * cq + 0) * 65 + px];
            v.y = s33[(4 * cq + 1) * 65 + px];
            v.z = s33[(4 * cq + 2) * 65 + px];
            v.w = s33[(4 * cq + 3) * 65 + px];
            *reinterpret_cast<float4*>(g_x2 + (pix0 + px) * C + 4 * cq) = v;
        }
    }

    // input_proj GEMM from xsT -> padded interior
    {
        int c = t & 63;
        int px0 = (t >> 6) * 16;
        u64 acc[8];
        #pragma unroll
        for (int i = 0; i < 8; i++) acc[i] = 0ull;
        #pragma unroll 4
        for (int k = 0; k < 64; k++) {
            u64 wd = dup2(Ws[k * 64 + c]);
            const ulonglong2* xr = reinterpret_cast<const ulonglong2*>(xsT + k * 72 + px0);
            ulonglong2 p0 = xr[0], p1 = xr[1];
            fma2(acc[0], p0.x, wd); fma2(acc[1], p0.y, wd);
            fma2(acc[2], p1.x, wd); fma2(acc[3], p1.y, wd);
            ulonglong2 p2 = xr[2], p3 = xr[3];
            fma2(acc[4], p2.x, wd); fma2(acc[5], p2.y, wd);
            fma2(acc[6], p3.x, wd); fma2(acc[7], p3.y, wd);
        }
        float bias = ib[c];
        #pragma unroll
        for (int i = 0; i < 8; i++) {
            float2 r = up2(acc[i]);
            #pragma unroll
            for (int s = 0; s < 2; s++) {
                float val = (s ? r.y : r.x) + bias;
                int pix = pix0 + px0 + 2 * i + s;
                int nn = pix >> 12, hw = pix & 4095;
                int yy = hw >> 6, xx = hw & 63;
                g_xpad[((nn * HP + yy + 1) * HP + (xx + 1)) * C + c] = val;
            }
        }
    }
}

// ---------------- K3: dw+LN+GeLU + DCNv3 core + conv2/BN2 (32 px/block) ----------------
#define DWS 33    // dwsT px-stride (conflict-mitigating)

struct DcnSmem {
    union {                                     // 36096 B region
        struct {                                // live stages 0-1
            float Woff[64 * 72];                // 18432
            float Wmask[64 * 36];               //  9216
            float dwsT[64 * DWS];               //  8448 [c][px], stride 33
        } a;
        struct {                                // live stage 3
            float w4e[16][2][36][4];            // 18432
            unsigned short o4e[16][2][36][4];   //  9216
        } b;
        float Wconv[64 * 128];                  // 32768, live stages 4-5
    } U;
    float Woutp[64 * 64];                       // 16384
    union {                                     // 13824 B region
        struct {                                // live stages 1-3
            float offs[32][72];                 //  9216
            float mks[32][36];                  //  4608
        } o;
        float ys[32 * 65];                      //  8320, live stages 4-5
    } V;
    float dcnsT[64 * 36];                       //  9216  [c][px]
    float scs[CO], shs[CO];                     //  1024
};                                              // 76544 B -> 2 blocks/SM

__global__ void __launch_bounds__(512, 2)
k_dcn(const float* __restrict__ dw_w, const float* __restrict__ dw_b,
      const float* __restrict__ ln_g, const float* __restrict__ ln_b,
      const float* __restrict__ off_w, const float* __restrict__ off_b,
      const float* __restrict__ mask_w, const float* __restrict__ mask_b,
      const float* __restrict__ outp_w, const float* __restrict__ outp_b,
      const float* __restrict__ bn1_g, const float* __restrict__ bn1_b,
      const float* __restrict__ bn1_m, const float* __restrict__ bn1_v,
      const float* __restrict__ conv_w, const float* __restrict__ conv_b,
      const float* __restrict__ bn2_g, const float* __restrict__ bn2_b,
      const float* __restrict__ bn2_m, const float* __restrict__ bn2_v,
      float* __restrict__ out) {
    extern __shared__ char smraw[];
    DcnSmem& sm = *reinterpret_cast<DcnSmem*>(smraw);
    int t = threadIdx.x;
    int pixbase = blockIdx.x * 32;
    int warp = t >> 5, lane = t & 31;

    // ---- stage 0: Woff/Wmask loads + BN2 consts + FUSED dw-conv+LN+GeLU -> dwsT ----
    {
        float4* dst = reinterpret_cast<float4*>(sm.U.a.Woff);
        const float4* src = reinterpret_cast<const float4*>(off_w);
        for (int i = t; i < 64 * 72 / 4; i += 512) dst[i] = src[i];
        dst = reinterpret_cast<float4*>(sm.U.a.Wmask);
        src = reinterpret_cast<const float4*>(mask_w);
        for (int i = t; i < 64 * 36 / 4; i += 512) dst[i] = src[i];
        if (t < 128) {
            float sc = bn2_g[t] * rsqrtf(bn2_v[t] + 1e-5f);
            sm.scs[t] = sc;
            sm.shs[t] = sc * (conv_b[t] - bn2_m[t]) + bn2_b[t];
        }
    }
    {
        // dw 3x3 + LN + GeLU: warp = 2 px, lane = (sub, ch-quad)
        int sub = lane >> 4;
        int pxt = warp * 2 + sub;
        int pix = pixbase + pxt;
        int n = pix >> 12, hw = pix & 4095;
        int y = hw >> 6, xx = hw & 63;
        int c0 = (lane & 15) * 4;
        float4 a = *reinterpret_cast<const float4*>(dw_b + c0);
        if (y >= 1 && y <= HH - 2 && xx >= 1 && xx <= WW - 2) {
            const float* base = g_x2 + ((n * HWP) + (y - 1) * WW + (xx - 1)) * C + c0;
            #pragma unroll
            for (int ky = 0; ky < 3; ky++) {
                #pragma unroll
                for (int kx = 0; kx < 3; kx++) {
                    float4 xv = *reinterpret_cast<const float4*>(base + (ky * WW + kx) * C);
                    float4 ww = *reinterpret_cast<const float4*>(dw_w + (ky * 3 + kx) * C + c0);
                    a.x += xv.x * ww.x; a.y += xv.y * ww.y;
                    a.z += xv.z * ww.z; a.w += xv.w * ww.w;
                }
            }
        } else {
            #pragma unroll
            for (int ky = 0; ky < 3; ky++) {
                int yy = y + ky - 1;
                if (yy < 0 || yy >= HH) continue;
                #pragma unroll
                for (int kx = 0; kx < 3; kx++) {
                    int xc = xx + kx - 1;
                    if (xc < 0 || xc >= WW) continue;
                    float4 xv = *reinterpret_cast<const float4*>(g_x2 + ((n * HWP) + yy * WW + xc) * C + c0);
                    float4 ww = *reinterpret_cast<const float4*>(dw_w + (ky * 3 + kx) * C + c0);
                    a.x += xv.x * ww.x; a.y += xv.y * ww.y;
                    a.z += xv.z * ww.z; a.w += xv.w * ww.w;
                }
            }
        }
        float s = a.x + a.y + a.z + a.w;
        float q = a.x * a.x + a.y * a.y + a.z * a.z + a.w * a.w;
        #pragma unroll
        for (int o = 8; o >= 1; o >>= 1) {
            s += __shfl_xor_sync(0xffffffffu, s, o);
            q += __shfl_xor_sync(0xffffffffu, q, o);
        }
        float mean = s * (1.f / 64.f);
        float var = q * (1.f / 64.f) - mean * mean;
        float rstd = rsqrtf(var + 1e-6f);
        float4 lg = *reinterpret_cast<const float4*>(ln_g + c0);
        float4 lb = *reinterpret_cast<const float4*>(ln_b + c0);
        float v;
        v = lg.x * (a.x - mean) * rstd + lb.x;
        sm.U.a.dwsT[(c0 + 0) * DWS + pxt] = 0.5f * v * (1.f + erff(v * 0.70710678118654752f));
        v = lg.y * (a.y - mean) * rstd + lb.y;
        sm.U.a.dwsT[(c0 + 1) * DWS + pxt] = 0.5f * v * (1.f + erff(v * 0.70710678118654752f));
        v = lg.z * (a.z - mean) * rstd + lb.z;
        sm.U.a.dwsT[(c0 + 2) * DWS + pxt] = 0.5f * v * (1.f + erff(v * 0.70710678118654752f));
        v = lg.w * (a.w - mean) * rstd + lb.w;
        sm.U.a.dwsT[(c0 + 3) * DWS + pxt] = 0.5f * v * (1.f + erff(v * 0.70710678118654752f));
    }
    __syncthreads();

    // ---- stage 1: off/mask GEMM. lane = px, warp = 12 j's (9 warps).
    //      Warps 9..15 load Woutp concurrently.
    if (warp < 9) {
        int j0 = warp * 12;
        bool isOff = j0 < 72;
        const float* wbase = isOff ? (sm.U.a.Woff + j0) : (sm.U.a.Wmask + (j0 - 72));
        int stride = isOff ? 72 : 36;
        u64 acc[6];
        #pragma unroll
        for (int i = 0; i < 6; i++) acc[i] = 0ull;
        #pragma unroll 4
        for (int k = 0; k < 64; k++) {
            u64 d = dup2(sm.U.a.dwsT[k * DWS + lane]);
            const ulonglong2* wr = reinterpret_cast<const ulonglong2*>(wbase + k * stride);
            ulonglong2 wa = wr[0], wb = wr[1], wc = wr[2];
            fma2(acc[0], d, wa.x); fma2(acc[1], d, wa.y);
            fma2(acc[2], d, wb.x); fma2(acc[3], d, wb.y);
            fma2(acc[4], d, wc.x); fma2(acc[5], d, wc.y);
        }
        const float* bb = isOff ? (off_b + j0) : (mask_b + (j0 - 72));
        float* orow = isOff ? (&sm.V.o.offs[lane][j0]) : (&sm.V.o.mks[lane][j0 - 72]);
        #pragma unroll
        for (int i = 0; i < 6; i++) {
            float2 r = up2(acc[i]);
            orow[2 * i]     = r.x + bb[2 * i];
            orow[2 * i + 1] = r.y + bb[2 * i + 1];
        }
    } else {
        float4* dst = reinterpret_cast<float4*>(sm.Woutp);
        const float4* src = reinterpret_cast<const float4*>(outp_w);
        for (int i = t - 288; i < 64 * 64 / 4; i += 224) dst[i] = src[i];
    }
    __syncthreads();

    // ---- stage 2: softmax per (px, group) ----
    if (t < 128) {
        int px = t >> 2, g = t & 3;
        float* mk = sm.V.o.mks[px] + g * 9;
        float mx = -1e30f;
        #pragma unroll
        for (int p = 0; p < 9; p++) mx = fmaxf(mx, mk[p]);
        float smx = 0.f;
        float e[9];
        #pragma unroll
        for (int p = 0; p < 9; p++) { e[p] = expf(mk[p] - mx); smx += e[p]; }
        float inv = 1.f / smx;
        #pragma unroll
        for (int p = 0; p < 9; p++) mk[p] = e[p] * inv;
    }
    __syncthreads();

    // ---- stage 3: bilinear precompute (mask folded, 2 px) + combined gather ----
    {
        #pragma unroll
        for (int sub2 = 0; sub2 < 2; sub2++) {
            int px = warp * 2 + sub2;
            int pix = pixbase + px;
            int hw = pix & 4095;
            int y = hw >> 6, x = hw & 63;
            for (int gp = lane; gp < 36; gp += 32) {
                int p = gp % 9;
                float fx = (float)x + (float)(p / 3) + sm.V.o.offs[px][gp * 2 + 0];
                float fy = (float)y + (float)(p % 3) + sm.V.o.offs[px][gp * 2 + 1];
                float fy0 = floorf(fy), fx0 = floorf(fx);
                float wy = fy - fy0, wx = fx - fx0;
                int iy0 = (int)fy0, ix0 = (int)fx0;
                int iy1 = iy0 + 1, ix1 = ix0 + 1;
                float vy0 = (iy0 >= 0 && iy0 < HP) ? 1.f : 0.f;
                float vy1 = (iy1 >= 0 && iy1 < HP) ? 1.f : 0.f;
                float vx0 = (ix0 >= 0 && ix0 < HP) ? 1.f : 0.f;
                float vx1 = (ix1 >= 0 && ix1 < HP) ? 1.f : 0.f;
                int cy0 = min(max(iy0, 0), HP - 1), cy1 = min(max(iy1, 0), HP - 1);
                int cx0 = min(max(ix0, 0), HP - 1), cx1 = min(max(ix1, 0), HP - 1);
                float m = sm.V.o.mks[px][gp];
                sm.U.b.w4e[warp][sub2][gp][0] = m * (1.f - wy) * (1.f - wx) * vy0 * vx0;
                sm.U.b.w4e[warp][sub2][gp][1] = m * (1.f - wy) * wx * vy0 * vx1;
                sm.U.b.w4e[warp][sub2][gp][2] = m * wy * (1.f - wx) * vy1 * vx0;
                sm.U.b.w4e[warp][sub2][gp][3] = m * wy * wx * vy1 * vx1;
                ushort4 oc;
                oc.x = (unsigned short)(cy0 * HP + cx0);
                oc.y = (unsigned short)(cy0 * HP + cx1);
                oc.z = (unsigned short)(cy1 * HP + cx0);
                oc.w = (unsigned short)(cy1 * HP + cx1);
                *reinterpret_cast<ushort4*>(&sm.U.b.o4e[warp][sub2][gp][0]) = oc;
            }
        }
        __syncwarp();
        // combined gather: lane = (sub, ch-quad); float4 (2x f32x2) per lane
        int sub = lane >> 4;
        int cq = lane & 15;
        int c0 = cq * 4;
        int g = cq >> 2;
        int px = warp * 2 + sub;
        int pix = pixbase + px;
        int n = pix >> 12;
        const float* xpn = g_xpad + n * HP * HP * C;
        u64 ax = 0ull, ay = 0ull;
        #pragma unroll
        for (int p = 0; p < 9; p++) {
            int gp = g * 9 + p;
            float4 ww = *reinterpret_cast<const float4*>(&sm.U.b.w4e[warp][sub][gp][0]);
            ushort4 oo = *reinterpret_cast<const ushort4*>(&sm.U.b.o4e[warp][sub][gp][0]);
            ulonglong2 x0 = *reinterpret_cast<const ulonglong2*>(xpn + (int)oo.x * C + c0);
            ulonglong2 x1 = *reinterpret_cast<const ulonglong2*>(xpn + (int)oo.y * C + c0);
            ulonglong2 x2 = *reinterpret_cast<const ulonglong2*>(xpn + (int)oo.z * C + c0);
            ulonglong2 x3 = *reinterpret_cast<const ulonglong2*>(xpn + (int)oo.w * C + c0);
            u64 w0 = dup2(ww.x), w1 = dup2(ww.y), w2 = dup2(ww.z), w3 = dup2(ww.w);
            fma2(ax, w0, x0.x); fma2(ay, w0, x0.y);
            fma2(ax, w1, x1.x); fma2(ay, w1, x1.y);
            fma2(ax, w2, x2.x); fma2(ay, w2, x2.y);
            fma2(ax, w3, x3.x); fma2(ay, w3, x3.y);
        }
        float2 r0 = up2(ax), r1 = up2(ay);
        sm.dcnsT[(c0 + 0) * 36 + px] = r0.x;
        sm.dcnsT[(c0 + 1) * 36 + px] = r0.y;
        sm.dcnsT[(c0 + 2) * 36 + px] = r1.x;
        sm.dcnsT[(c0 + 3) * 36 + px] = r1.y;
    }
    __syncthreads();

    // ---- stage 4: output_proj + BN1 + relu -> smem ys (warps 0-7);
    //      warps 8-15 load conv weights into the dead U region ----
    if (warp < 8) {
        int cp = lane * 2;
        int px0 = warp * 4;
        u64 acc[4];
        #pragma unroll
        for (int i = 0; i < 4; i++) acc[i] = 0ull;
        #pragma unroll 4
        for (int k = 0; k < 64; k++) {
            u64 w2 = *reinterpret_cast<const u64*>(sm.Woutp + k * 64 + cp);   // coalesced
            float4 dv = *reinterpret_cast<const float4*>(sm.dcnsT + k * 36 + px0); // broadcast
            fma2(acc[0], dup2(dv.x), w2);
            fma2(acc[1], dup2(dv.y), w2);
            fma2(acc[2], dup2(dv.z), w2);
            fma2(acc[3], dup2(dv.w), w2);
        }
        float ob0 = outp_b[cp], ob1 = outp_b[cp + 1];
        float sc0 = bn1_g[cp] * rsqrtf(bn1_v[cp] + 1e-5f);
        float sc1 = bn1_g[cp + 1] * rsqrtf(bn1_v[cp + 1] + 1e-5f);
        float sh0 = bn1_b[cp] - sc0 * bn1_m[cp];
        float sh1 = bn1_b[cp + 1] - sc1 * bn1_m[cp + 1];
        #pragma unroll
        for (int i = 0; i < 4; i++) {
            float2 r = up2(acc[i]);
            int px = px0 + i;
            sm.V.ys[px * 65 + cp]     = fmaxf(sc0 * (r.x + ob0) + sh0, 0.f);
            sm.V.ys[px * 65 + cp + 1] = fmaxf(sc1 * (r.y + ob1) + sh1, 0.f);
        }
    } else {
        // load conv_w (64x128 = 32KB) into U.Wconv
        float4* dst = reinterpret_cast<float4*>(sm.U.Wconv);
        const float4* src = reinterpret_cast<const float4*>(conv_w);
        for (int i = t - 256; i < 64 * 128 / 4; i += 256) dst[i] = src[i];
    }
    __syncthreads();

    // ---- stage 5: conv2 1x1 64->128 + BN2 + relu, direct to out ----
    {
        int px = t & 31;
        int co0 = (t >> 5) * 8;           // 16 groups of 8 co
        int pix = pixbase + px;
        int n = pix >> 12, hw = pix & 4095;
        const float* yrow = sm.V.ys + px * 65;
        u64 acc0 = 0ull, acc1 = 0ull, acc2 = 0ull, acc3 = 0ull;
        #pragma unroll 4
        for (int k = 0; k < 64; k++) {
            u64 yd = dup2(yrow[k]);
            const ulonglong2* wr = reinterpret_cast<const ulonglong2*>(sm.U.Wconv + k * 128 + co0);
            ulonglong2 w01 = wr[0], w23 = wr[1];
            fma2(acc0, w01.x, yd); fma2(acc1, w01.y, yd);
            fma2(acc2, w23.x, yd); fma2(acc3, w23.y, yd);
        }
        u64 accs[4] = {acc0, acc1, acc2, acc3};
        #pragma unroll
        for (int i = 0; i < 4; i++) {
            float2 r = up2(accs[i]);
            #pragma unroll
            for (int s = 0; s < 2; s++) {
                int co = co0 + 2 * i + s;
                float val = sm.scs[co] * (s ? r.y : r.x) + sm.shs[co];
                out[(n * CO + co) * HWP + hw] = fmaxf(val, 0.f);
            }
        }
    }
}

// ---------------- launcher ----------------
extern "C" void kernel_launch(void* const* d_in, const int* in_sizes, int n_in,
                              void* d_out, int out_size) {
    const float* x       = (const float*)d_in[0];
    const float* refl    = (const float*)d_in[1];
    const float* gain_w1 = (const float*)d_in[2];
    const float* gain_b1 = (const float*)d_in[3];
    const float* gain_w2 = (const float*)d_in[4];
    const float* gain_b2 = (const float*)d_in[5];
    const float* tap_w   = (const float*)d_in[6];
    const float* tap_b   = (const float*)d_in[7];
    const float* dw_w    = (const float*)d_in[8];
    const float* dw_b    = (const float*)d_in[9];
    const float* ln_g    = (const float*)d_in[10];
    const float* ln_b    = (const float*)d_in[11];
    const float* inp_w   = (const float*)d_in[12];
    const float* inp_b   = (const float*)d_in[13];
    const float* off_w   = (const float*)d_in[14];
    const float* off_b   = (const float*)d_in[15];
    const float* mask_w  = (const float*)d_in[16];
    const float* mask_b  = (const float*)d_in[17];
    const float* outp_w  = (const float*)d_in[18];
    const float* outp_b  = (const float*)d_in[19];
    const float* conv_w  = (const float*)d_in[20];
    const float* conv_b  = (const float*)d_in[21];
    const float* bn1_g   = (const float*)d_in[22];
    const float* bn1_b   = (const float*)d_in[23];
    const float* bn1_m   = (const float*)d_in[24];
    const float* bn1_v   = (const float*)d_in[25];
    const float* bn2_g   = (const float*)d_in[26];
    const float* bn2_b   = (const float*)d_in[27];
    const float* bn2_m   = (const float*)d_in[28];
    const float* bn2_v   = (const float*)d_in[29];
    float* out = (float*)d_out;

    cudaFuncSetAttribute(k_dcn, cudaFuncAttributeMaxDynamicSharedMemorySize,
                         (int)sizeof(DcnSmem));
    cudaFuncSetAttribute(k_fuse2, cudaFuncAttributeMaxDynamicSharedMemorySize,
                         FUSE_SMEM);

    k_pool<<<NN * C, 1024>>>(x);
    k_fuse2<<<NN * HWP / 64, 256, FUSE_SMEM>>>(x, refl, tap_w, tap_b,
                                               gain_w1, gain_b1, gain_w2, gain_b2,
                                               inp_w, inp_b);
    k_dcn<<<NN * HWP / 32, 512, sizeof(DcnSmem)>>>(dw_w, dw_b, ln_g, ln_b,
                                                   off_w, off_b, mask_w, mask_b,
                                                   outp_w, outp_b, bn1_g, bn1_b, bn1_m, bn1_v,
                                                   conv_w, conv_b, bn2_g, bn2_b, bn2_m, bn2_v,
                                                   out);
}

// round 17
// speedup vs baseline: 1.0619x; 1.0619x over previous
#include <cuda_runtime.h>
#include <math.h>

#define NN 8
#define C  64
#define HH 64
#define WW 64
#define HWP 4096            // H*W
#define HP 66               // padded
#define CO 128

typedef unsigned long long u64;

// ---- f32x2 helpers (exact fp32, 2 lanes per instruction) ----
__device__ __forceinline__ u64 dup2(float v) {
    u64 r; asm("mov.b64 %0,{%1,%1};" : "=l"(r) : "f"(v)); return r;
}
__device__ __forceinline__ void fma2(u64& d, u64 a, u64 b) {
    asm("fma.rn.f32x2 %0,%1,%2,%0;" : "+l"(d) : "l"(a), "l"(b));
}
__device__ __forceinline__ float2 up2(u64 v) {
    float2 r; asm("mov.b64 {%0,%1},%2;" : "=f"(r.x), "=f"(r.y) : "l"(v)); return r;
}

// ---------------- scratch ----------------
__device__ float g_pooled[NN * C];
__device__ __align__(16) float g_x2[NN * HWP * C];
__device__ __align__(16) float g_xpad[NN * HP * HP * C];   // zero-init; border never written

// ---------------- K1: global average pool (512 thr, 2 float4/thread) ----------------
__global__ void __launch_bounds__(512)
k_pool(const float* __restrict__ x) {
    int nc = blockIdx.x;
    int t = threadIdx.x;
    const float4* xr = reinterpret_cast<const float4*>(x + nc * HWP);
    float4 v0 = xr[t];
    float4 v1 = xr[t + 512];
    float a = ((v0.x + v0.y) + (v0.z + v0.w)) + ((v1.x + v1.y) + (v1.z + v1.w));
    #pragma unroll
    for (int o = 16; o >= 1; o >>= 1) a += __shfl_xor_sync(0xffffffffu, a, o);
    __shared__ float red[16];
    if ((t & 31) == 0) red[t >> 5] = a;
    __syncthreads();
    if (t < 16) {
        float s = red[t];
        #pragma unroll
        for (int o = 8; o >= 1; o >>= 1) s += __shfl_xor_sync(0xffffu, s, o);
        if (t == 0) g_pooled[nc] = s * (1.f / (float)HWP);
    }
}

// ---------------- K2 (fused): gain MLP + gain/refl fuse + input_proj GEMM ----------------
// 64 px/block, 512 blocks. Produces g_x2 AND g_xpad in one pass.
#define FUSE_SMEM ((64 * 65 + 64 * 72 + 64 * 64) * 4)

__global__ void __launch_bounds__(256)
k_fuse2(const float* __restrict__ x, const float* __restrict__ refl,
        const float* __restrict__ tap_w, const float* __restrict__ tap_b,
        const float* __restrict__ w1, const float* __restrict__ b1,
        const float* __restrict__ w2, const float* __restrict__ b2,
        const float* __restrict__ iw, const float* __restrict__ ib) {
    extern __shared__ __align__(16) float dyn[];
    float* s33 = dyn;                  // [c][px] stride 65 (conflict-free transpose reads)
    float* xsT = dyn + 64 * 65;        // [k][px] stride 72 (16B-aligned rows for GEMM)
    float* Ws  = xsT + 64 * 72;        // inp weights [k][c]
    __shared__ float pl[C];
    __shared__ float h[16];
    __shared__ float gn[C];
    __shared__ float rfl[64];
    int t = threadIdx.x;
    int pix0 = blockIdx.x * 64;
    int n = pix0 >> 12;
    int hw0 = pix0 & 4095;

    // weights + pooled + refl
    {
        const float4* wsrc = reinterpret_cast<const float4*>(iw);
        float4* wdst = reinterpret_cast<float4*>(Ws);
        for (int i = t; i < 64 * 64 / 4; i += 256) wdst[i] = wsrc[i];
    }
    if (t < 64) pl[t] = g_pooled[n * C + t];
    if (t >= 64 && t < 128) rfl[t - 64] = refl[n * HWP + hw0 + (t - 64)];
    __syncthreads();
    if (t < 16) {
        float a = b1[t];
        #pragma unroll 16
        for (int c = 0; c < C; c++) a += pl[c] * w1[c * 16 + t];
        h[t] = fmaxf(a, 0.f);
    }
    __syncthreads();
    if (t < 64) {
        float a = b2[t];
        #pragma unroll
        for (int j = 0; j < 16; j++) a += h[j] * w2[j * C + t];
        gn[t] = 1.f + 1.f / (1.f + expf(-a));
    }
    __syncthreads();

    // load x + apply gain + refl; write both smem copies
    {
        int px = t & 63;
        int ch = t >> 6;               // 0..3
        float rv = rfl[px];
        #pragma unroll 4
        for (int i = 0; i < 16; i++) {
            int c = i * 4 + ch;
            float val = x[(n * C + c) * HWP + hw0 + px] * gn[c];
            val += fmaxf(rv * tap_w[c] + tap_b[c], 0.f);
            s33[c * 65 + px] = val;
            xsT[c * 72 + px] = val;
        }
    }
    __syncthreads();

    // write g_x2 coalesced (transpose via s33)
    {
        int cq = t & 15;
        int pxb = t >> 4;              // 0..15
        #pragma unroll
        for (int pass = 0; pass < 4; pass++) {
            int px = pass * 16 + pxb;
            float4 v;
            v.x = s33[(4 * cq + 0) * 65 + px];
            v.y = s33[(4 * cq + 1) * 65 + px];
            v.z = s33[(4 * cq + 2) * 65 + px];
            v.w = s33[(4 * cq + 3) * 65 + px];
            *reinterpret_cast<float4*>(g_x2 + (pix0 + px) * C + 4 * cq) = v;
        }
    }

    // input_proj GEMM from xsT -> padded interior
    {
        int c = t & 63;
        int px0 = (t >> 6) * 16;
        u64 acc[8];
        #pragma unroll
        for (int i = 0; i < 8; i++) acc[i] = 0ull;
        #pragma unroll 4
        for (int k = 0; k < 64; k++) {
            u64 wd = dup2(Ws[k * 64 + c]);
            const ulonglong2* xr = reinterpret_cast<const ulonglong2*>(xsT + k * 72 + px0);
            ulonglong2 p0 = xr[0], p1 = xr[1];
            fma2(acc[0], p0.x, wd); fma2(acc[1], p0.y, wd);
            fma2(acc[2], p1.x, wd); fma2(acc[3], p1.y, wd);
            ulonglong2 p2 = xr[2], p3 = xr[3];
            fma2(acc[4], p2.x, wd); fma2(acc[5], p2.y, wd);
            fma2(acc[6], p3.x, wd); fma2(acc[7], p3.y, wd);
        }
        float bias = ib[c];
        #pragma unroll
        for (int i = 0; i < 8; i++) {
            float2 r = up2(acc[i]);
            #pragma unroll
            for (int s = 0; s < 2; s++) {
                float val = (s ? r.y : r.x) + bias;
                int pix = pix0 + px0 + 2 * i + s;
                int nn = pix >> 12, hw = pix & 4095;
                int yy = hw >> 6, xx = hw & 63;
                g_xpad[((nn * HP + yy + 1) * HP + (xx + 1)) * C + c] = val;
            }
        }
    }
}

// ---------------- K3: dw+LN+GeLU + DCNv3 core + conv2/BN2 (32 px/block) ----------------
#define DWS 33    // dwsT px-stride (conflict-mitigating)

struct DcnSmem {
    union {                                     // 36096 B region
        struct {                                // live stages 0-1
            float Woff[64 * 72];                // 18432
            float Wmask[64 * 36];               //  9216
            float dwsT[64 * DWS];               //  8448 [c][px], stride 33
        } a;
        struct {                                // live stage 3
            float w4e[16][2][36][4];            // 18432
            unsigned short o4e[16][2][36][4];   //  9216
        } b;
        float Wconv[64 * 128];                  // 32768, live stages 4-5
    } U;
    float Woutp[64 * 64];                       // 16384
    union {                                     // 13824 B region
        struct {                                // live stages 1-3
            float offs[32][72];                 //  9216
            float mks[32][36];                  //  4608
        } o;
        float ys[32 * 65];                      //  8320, live stages 4-5
    } V;
    float dcnsT[64 * 36];                       //  9216  [c][px]
    float scs[CO], shs[CO];                     //  1024
};                                              // 76544 B -> 2 blocks/SM

__global__ void __launch_bounds__(512, 2)
k_dcn(const float* __restrict__ dw_w, const float* __restrict__ dw_b,
      const float* __restrict__ ln_g, const float* __restrict__ ln_b,
      const float* __restrict__ off_w, const float* __restrict__ off_b,
      const float* __restrict__ mask_w, const float* __restrict__ mask_b,
      const float* __restrict__ outp_w, const float* __restrict__ outp_b,
      const float* __restrict__ bn1_g, const float* __restrict__ bn1_b,
      const float* __restrict__ bn1_m, const float* __restrict__ bn1_v,
      const float* __restrict__ conv_w, const float* __restrict__ conv_b,
      const float* __restrict__ bn2_g, const float* __restrict__ bn2_b,
      const float* __restrict__ bn2_m, const float* __restrict__ bn2_v,
      float* __restrict__ out) {
    extern __shared__ char smraw[];
    DcnSmem& sm = *reinterpret_cast<DcnSmem*>(smraw);
    int t = threadIdx.x;
    int pixbase = blockIdx.x * 32;
    int warp = t >> 5, lane = t & 31;

    // ---- stage 0: Woff/Wmask loads + BN2 consts + FUSED dw-conv+LN+GeLU -> dwsT ----
    {
        float4* dst = reinterpret_cast<float4*>(sm.U.a.Woff);
        const float4* src = reinterpret_cast<const float4*>(off_w);
        for (int i = t; i < 64 * 72 / 4; i += 512) dst[i] = src[i];
        dst = reinterpret_cast<float4*>(sm.U.a.Wmask);
        src = reinterpret_cast<const float4*>(mask_w);
        for (int i = t; i < 64 * 36 / 4; i += 512) dst[i] = src[i];
        if (t < 128) {
            float sc = bn2_g[t] * rsqrtf(bn2_v[t] + 1e-5f);
            sm.scs[t] = sc;
            sm.shs[t] = sc * (conv_b[t] - bn2_m[t]) + bn2_b[t];
        }
    }
    {
        // dw 3x3 + LN + GeLU: warp = 2 px, lane = (sub, ch-quad)
        int sub = lane >> 4;
        int pxt = warp * 2 + sub;
        int pix = pixbase + pxt;
        int n = pix >> 12, hw = pix & 4095;
        int y = hw >> 6, xx = hw & 63;
        int c0 = (lane & 15) * 4;
        float4 a = *reinterpret_cast<const float4*>(dw_b + c0);
        if (y >= 1 && y <= HH - 2 && xx >= 1 && xx <= WW - 2) {
            const float* base = g_x2 + ((n * HWP) + (y - 1) * WW + (xx - 1)) * C + c0;
            #pragma unroll
            for (int ky = 0; ky < 3; ky++) {
                #pragma unroll
                for (int kx = 0; kx < 3; kx++) {
                    float4 xv = *reinterpret_cast<const float4*>(base + (ky * WW + kx) * C);
                    float4 ww = *reinterpret_cast<const float4*>(dw_w + (ky * 3 + kx) * C + c0);
                    a.x += xv.x * ww.x; a.y += xv.y * ww.y;
                    a.z += xv.z * ww.z; a.w += xv.w * ww.w;
                }
            }
        } else {
            #pragma unroll
            for (int ky = 0; ky < 3; ky++) {
                int yy = y + ky - 1;
                if (yy < 0 || yy >= HH) continue;
                #pragma unroll
                for (int kx = 0; kx < 3; kx++) {
                    int xc = xx + kx - 1;
                    if (xc < 0 || xc >= WW) continue;
                    float4 xv = *reinterpret_cast<const float4*>(g_x2 + ((n * HWP) + yy * WW + xc) * C + c0);
                    float4 ww = *reinterpret_cast<const float4*>(dw_w + (ky * 3 + kx) * C + c0);
                    a.x += xv.x * ww.x; a.y += xv.y * ww.y;
                    a.z += xv.z * ww.z; a.w += xv.w * ww.w;
                }
            }
        }
        float s = a.x + a.y + a.z + a.w;
        float q = a.x * a.x + a.y * a.y + a.z * a.z + a.w * a.w;
        #pragma unroll
        for (int o = 8; o >= 1; o >>= 1) {
            s += __shfl_xor_sync(0xffffffffu, s, o);
            q += __shfl_xor_sync(0xffffffffu, q, o);
        }
        float mean = s * (1.f / 64.f);
        float var = q * (1.f / 64.f) - mean * mean;
        float rstd = rsqrtf(var + 1e-6f);
        float4 lg = *reinterpret_cast<const float4*>(ln_g + c0);
        float4 lb = *reinterpret_cast<const float4*>(ln_b + c0);
        float v;
        v = lg.x * (a.x - mean) * rstd + lb.x;
        sm.U.a.dwsT[(c0 + 0) * DWS + pxt] = 0.5f * v * (1.f + erff(v * 0.70710678118654752f));
        v = lg.y * (a.y - mean) * rstd + lb.y;
        sm.U.a.dwsT[(c0 + 1) * DWS + pxt] = 0.5f * v * (1.f + erff(v * 0.70710678118654752f));
        v = lg.z * (a.z - mean) * rstd + lb.z;
        sm.U.a.dwsT[(c0 + 2) * DWS + pxt] = 0.5f * v * (1.f + erff(v * 0.70710678118654752f));
        v = lg.w * (a.w - mean) * rstd + lb.w;
        sm.U.a.dwsT[(c0 + 3) * DWS + pxt] = 0.5f * v * (1.f + erff(v * 0.70710678118654752f));
    }
    __syncthreads();

    // ---- stage 1: off/mask GEMM. lane = px, warp = 12 j's (9 warps).
    //      Warps 9..15 load Woutp concurrently.
    if (warp < 9) {
        int j0 = warp * 12;
        bool isOff = j0 < 72;
        const float* wbase = isOff ? (sm.U.a.Woff + j0) : (sm.U.a.Wmask + (j0 - 72));
        int stride = isOff ? 72 : 36;
        u64 acc[6];
        #pragma unroll
        for (int i = 0; i < 6; i++) acc[i] = 0ull;
        #pragma unroll 4
        for (int k = 0; k < 64; k++) {
            u64 d = dup2(sm.U.a.dwsT[k * DWS + lane]);
            const ulonglong2* wr = reinterpret_cast<const ulonglong2*>(wbase + k * stride);
            ulonglong2 wa = wr[0], wb = wr[1], wc = wr[2];
            fma2(acc[0], d, wa.x); fma2(acc[1], d, wa.y);
            fma2(acc[2], d, wb.x); fma2(acc[3], d, wb.y);
            fma2(acc[4], d, wc.x); fma2(acc[5], d, wc.y);
        }
        const float* bb = isOff ? (off_b + j0) : (mask_b + (j0 - 72));
        float* orow = isOff ? (&sm.V.o.offs[lane][j0]) : (&sm.V.o.mks[lane][j0 - 72]);
        #pragma unroll
        for (int i = 0; i < 6; i++) {
            float2 r = up2(acc[i]);
            orow[2 * i]     = r.x + bb[2 * i];
            orow[2 * i + 1] = r.y + bb[2 * i + 1];
        }
    } else {
        float4* dst = reinterpret_cast<float4*>(sm.Woutp);
        const float4* src = reinterpret_cast<const float4*>(outp_w);
        for (int i = t - 288; i < 64 * 64 / 4; i += 224) dst[i] = src[i];
    }
    __syncthreads();

    // ---- stage 2: softmax per (px, group) ----
    if (t < 128) {
        int px = t >> 2, g = t & 3;
        float* mk = sm.V.o.mks[px] + g * 9;
        float mx = -1e30f;
        #pragma unroll
        for (int p = 0; p < 9; p++) mx = fmaxf(mx, mk[p]);
        float smx = 0.f;
        float e[9];
        #pragma unroll
        for (int p = 0; p < 9; p++) { e[p] = expf(mk[p] - mx); smx += e[p]; }
        float inv = 1.f / smx;
        #pragma unroll
        for (int p = 0; p < 9; p++) mk[p] = e[p] * inv;
    }
    __syncthreads();

    // ---- stage 3: bilinear precompute (mask folded, 2 px) + combined gather ----
    {
        #pragma unroll
        for (int sub2 = 0; sub2 < 2; sub2++) {
            int px = warp * 2 + sub2;
            int pix = pixbase + px;
            int hw = pix & 4095;
            int y = hw >> 6, x = hw & 63;
            for (int gp = lane; gp < 36; gp += 32) {
                int p = gp % 9;
                float fx = (float)x + (float)(p / 3) + sm.V.o.offs[px][gp * 2 + 0];
                float fy = (float)y + (float)(p % 3) + sm.V.o.offs[px][gp * 2 + 1];
                float fy0 = floorf(fy), fx0 = floorf(fx);
                float wy = fy - fy0, wx = fx - fx0;
                int iy0 = (int)fy0, ix0 = (int)fx0;
                int iy1 = iy0 + 1, ix1 = ix0 + 1;
                float vy0 = (iy0 >= 0 && iy0 < HP) ? 1.f : 0.f;
                float vy1 = (iy1 >= 0 && iy1 < HP) ? 1.f : 0.f;
                float vx0 = (ix0 >= 0 && ix0 < HP) ? 1.f : 0.f;
                float vx1 = (ix1 >= 0 && ix1 < HP) ? 1.f : 0.f;
                int cy0 = min(max(iy0, 0), HP - 1), cy1 = min(max(iy1, 0), HP - 1);
                int cx0 = min(max(ix0, 0), HP - 1), cx1 = min(max(ix1, 0), HP - 1);
                float m = sm.V.o.mks[px][gp];
                sm.U.b.w4e[warp][sub2][gp][0] = m * (1.f - wy) * (1.f - wx) * vy0 * vx0;
                sm.U.b.w4e[warp][sub2][gp][1] = m * (1.f - wy) * wx * vy0 * vx1;
                sm.U.b.w4e[warp][sub2][gp][2] = m * wy * (1.f - wx) * vy1 * vx0;
                sm.U.b.w4e[warp][sub2][gp][3] = m * wy * wx * vy1 * vx1;
                ushort4 oc;
                oc.x = (unsigned short)(cy0 * HP + cx0);
                oc.y = (unsigned short)(cy0 * HP + cx1);
                oc.z = (unsigned short)(cy1 * HP + cx0);
                oc.w = (unsigned short)(cy1 * HP + cx1);
                *reinterpret_cast<ushort4*>(&sm.U.b.o4e[warp][sub2][gp][0]) = oc;
            }
        }
        __syncwarp();
        // combined gather: lane = (sub, ch-quad); float4 (2x f32x2) per lane
        int sub = lane >> 4;
        int cq = lane & 15;
        int c0 = cq * 4;
        int g = cq >> 2;
        int px = warp * 2 + sub;
        int pix = pixbase + px;
        int n = pix >> 12;
        const float* xpn = g_xpad + n * HP * HP * C;
        u64 ax = 0ull, ay = 0ull;
        #pragma unroll
        for (int p = 0; p < 9; p++) {
            int gp = g * 9 + p;
            float4 ww = *reinterpret_cast<const float4*>(&sm.U.b.w4e[warp][sub][gp][0]);
            ushort4 oo = *reinterpret_cast<const ushort4*>(&sm.U.b.o4e[warp][sub][gp][0]);
            ulonglong2 x0 = *reinterpret_cast<const ulonglong2*>(xpn + (int)oo.x * C + c0);
            ulonglong2 x1 = *reinterpret_cast<const ulonglong2*>(xpn + (int)oo.y * C + c0);
            ulonglong2 x2 = *reinterpret_cast<const ulonglong2*>(xpn + (int)oo.z * C + c0);
            ulonglong2 x3 = *reinterpret_cast<const ulonglong2*>(xpn + (int)oo.w * C + c0);
            u64 w0 = dup2(ww.x), w1 = dup2(ww.y), w2 = dup2(ww.z), w3 = dup2(ww.w);
            fma2(ax, w0, x0.x); fma2(ay, w0, x0.y);
            fma2(ax, w1, x1.x); fma2(ay, w1, x1.y);
            fma2(ax, w2, x2.x); fma2(ay, w2, x2.y);
            fma2(ax, w3, x3.x); fma2(ay, w3, x3.y);
        }
        float2 r0 = up2(ax), r1 = up2(ay);
        sm.dcnsT[(c0 + 0) * 36 + px] = r0.x;
        sm.dcnsT[(c0 + 1) * 36 + px] = r0.y;
        sm.dcnsT[(c0 + 2) * 36 + px] = r1.x;
        sm.dcnsT[(c0 + 3) * 36 + px] = r1.y;
    }
    __syncthreads();

    // ---- stage 4: output_proj + BN1 + relu -> smem ys (warps 0-7);
    //      warps 8-15 load conv weights into the dead U region ----
    if (warp < 8) {
        int cp = lane * 2;
        int px0 = warp * 4;
        u64 acc[4];
        #pragma unroll
        for (int i = 0; i < 4; i++) acc[i] = 0ull;
        #pragma unroll 4
        for (int k = 0; k < 64; k++) {
            u64 w2 = *reinterpret_cast<const u64*>(sm.Woutp + k * 64 + cp);   // coalesced
            float4 dv = *reinterpret_cast<const float4*>(sm.dcnsT + k * 36 + px0); // broadcast
            fma2(acc[0], dup2(dv.x), w2);
            fma2(acc[1], dup2(dv.y), w2);
            fma2(acc[2], dup2(dv.z), w2);
            fma2(acc[3], dup2(dv.w), w2);
        }
        float ob0 = outp_b[cp], ob1 = outp_b[cp + 1];
        float sc0 = bn1_g[cp] * rsqrtf(bn1_v[cp] + 1e-5f);
        float sc1 = bn1_g[cp + 1] * rsqrtf(bn1_v[cp + 1] + 1e-5f);
        float sh0 = bn1_b[cp] - sc0 * bn1_m[cp];
        float sh1 = bn1_b[cp + 1] - sc1 * bn1_m[cp + 1];
        #pragma unroll
        for (int i = 0; i < 4; i++) {
            float2 r = up2(acc[i]);
            int px = px0 + i;
            sm.V.ys[px * 65 + cp]     = fmaxf(sc0 * (r.x + ob0) + sh0, 0.f);
            sm.V.ys[px * 65 + cp + 1] = fmaxf(sc1 * (r.y + ob1) + sh1, 0.f);
        }
    } else {
        // load conv_w (64x128 = 32KB) into U.Wconv
        float4* dst = reinterpret_cast<float4*>(sm.U.Wconv);
        const float4* src = reinterpret_cast<const float4*>(conv_w);
        for (int i = t - 256; i < 64 * 128 / 4; i += 256) dst[i] = src[i];
    }
    __syncthreads();

    // ---- stage 5: conv2 1x1 64->128 + BN2 + relu, direct to out ----
    {
        int px = t & 31;
        int co0 = (t >> 5) * 8;           // 16 groups of 8 co
        int pix = pixbase + px;
        int n = pix >> 12, hw = pix & 4095;
        const float* yrow = sm.V.ys + px * 65;
        u64 acc0 = 0ull, acc1 = 0ull, acc2 = 0ull, acc3 = 0ull;
        #pragma unroll 4
        for (int k = 0; k < 64; k++) {
            u64 yd = dup2(yrow[k]);
            const ulonglong2* wr = reinterpret_cast<const ulonglong2*>(sm.U.Wconv + k * 128 + co0);
            ulonglong2 w01 = wr[0], w23 = wr[1];
            fma2(acc0, w01.x, yd); fma2(acc1, w01.y, yd);
            fma2(acc2, w23.x, yd); fma2(acc3, w23.y, yd);
        }
        u64 accs[4] = {acc0, acc1, acc2, acc3};
        #pragma unroll
        for (int i = 0; i < 4; i++) {
            float2 r = up2(accs[i]);
            #pragma unroll
            for (int s = 0; s < 2; s++) {
                int co = co0 + 2 * i + s;
                float val = sm.scs[co] * (s ? r.y : r.x) + sm.shs[co];
                out[(n * CO + co) * HWP + hw] = fmaxf(val, 0.f);
            }
        }
    }
}

// ---------------- launcher ----------------
extern "C" void kernel_launch(void* const* d_in, const int* in_sizes, int n_in,
                              void* d_out, int out_size) {
    const float* x       = (const float*)d_in[0];
    const float* refl    = (const float*)d_in[1];
    const float* gain_w1 = (const float*)d_in[2];
    const float* gain_b1 = (const float*)d_in[3];
    const float* gain_w2 = (const float*)d_in[4];
    const float* gain_b2 = (const float*)d_in[5];
    const float* tap_w   = (const float*)d_in[6];
    const float* tap_b   = (const float*)d_in[7];
    const float* dw_w    = (const float*)d_in[8];
    const float* dw_b    = (const float*)d_in[9];
    const float* ln_g    = (const float*)d_in[10];
    const float* ln_b    = (const float*)d_in[11];
    const float* inp_w   = (const float*)d_in[12];
    const float* inp_b   = (const float*)d_in[13];
    const float* off_w   = (const float*)d_in[14];
    const float* off_b   = (const float*)d_in[15];
    const float* mask_w  = (const float*)d_in[16];
    const float* mask_b  = (const float*)d_in[17];
    const float* outp_w  = (const float*)d_in[18];
    const float* outp_b  = (const float*)d_in[19];
    const float* conv_w  = (const float*)d_in[20];
    const float* conv_b  = (const float*)d_in[21];
    const float* bn1_g   = (const float*)d_in[22];
    const float* bn1_b   = (const float*)d_in[23];
    const float* bn1_m   = (const float*)d_in[24];
    const float* bn1_v   = (const float*)d_in[25];
    const float* bn2_g   = (const float*)d_in[26];
    const float* bn2_b   = (const float*)d_in[27];
    const float* bn2_m   = (const float*)d_in[28];
    const float* bn2_v   = (const float*)d_in[29];
    float* out = (float*)d_out;

    cudaFuncSetAttribute(k_dcn, cudaFuncAttributeMaxDynamicSharedMemorySize,
                         (int)sizeof(DcnSmem));
    cudaFuncSetAttribute(k_fuse2, cudaFuncAttributeMaxDynamicSharedMemorySize,
                         FUSE_SMEM);

    k_pool<<<NN * C, 512>>>(x);
    k_fuse2<<<NN * HWP / 64, 256, FUSE_SMEM>>>(x, refl, tap_w, tap_b,
                                               gain_w1, gain_b1, gain_w2, gain_b2,
                                               inp_w, inp_b);
    k_dcn<<<NN * HWP / 32, 512, sizeof(DcnSmem)>>>(dw_w, dw_b, ln_g, ln_b,
                                                   off_w, off_b, mask_w, mask_b,
                                                   outp_w, outp_b, bn1_g, bn1_b, bn1_m, bn1_v,
                                                   conv_w, conv_b, bn2_g, bn2_b, bn2_m, bn2_v,
                                                   out);
}